// round 10
// baseline (speedup 1.0000x reference)
#include <cuda_runtime.h>
#include <math.h>

// Two-kernel split:
//   A: t[b] = argmax(target[b,:])          (reads target once, writes g_t)
//   B: out  = -mean log(y[b,t_b]+1e-8) + sum wtab[popc(t_b^c)]*y[b,c]/(B*N)
// N = 1024 (10 bits), wtab[0]=0, wtab[p]=6^p (exact in fp32).
// A: interleaved next-row prefetch at CPS=3 (proven ~6.9 TB/s).
// B: batched double-buffered rows (yv_a/yv_b ping-pong) at CPS=2 — 16 LDG.128
//    in flight per warp continuously, no reduce bubble.

#define NCLS   1024
#define MAXB   65536
#define SMS    152
#define TPB    256
#define WPB    (TPB / 32)

#define CPS_A  3
#define CPS_B  2
#define BLK_A  (SMS * CPS_A)
#define BLK_B  (SMS * CPS_B)

__device__ int      g_t[MAXB];
__device__ double   g_ce = 0.0;
__device__ double   g_pt = 0.0;
__device__ unsigned g_count = 0;

// ---------------------------------------------------------------- kernel A
__global__ __launch_bounds__(TPB, CPS_A)
void argmax_kernel(const float* __restrict__ tgt, int B) {
    const int tid  = threadIdx.x;
    const int lane = tid & 31;
    const int wid  = tid >> 5;

    const int gw = blockIdx.x * WPB + wid;
    const int nw = gridDim.x * WPB;

    float4 tv[8];
    {
        const float4* trow = (const float4*)(tgt + (size_t)gw * NCLS) + lane;
        #pragma unroll
        for (int it = 0; it < 8; it++)
            tv[it] = __ldcs(trow + it * 32);
    }

    for (int r = gw; r < B; r += nw) {
        const int  rn       = r + nw;
        const bool has_next = rn < B;                 // warp-uniform
        const float4* trowN = (const float4*)(tgt + (size_t)(has_next ? rn : r) * NCLS) + lane;

        // key = (fbits<<32)|(N-1-idx): positive uniforms -> bits monotonic;
        // complemented idx -> max-key picks FIRST max on ties.
        unsigned long long bk = 0ull;
        #pragma unroll
        for (int it = 0; it < 8; it++) {
            int c = (it * 32 + lane) * 4;
            unsigned long long k;
            k = ((unsigned long long)__float_as_uint(tv[it].x) << 32) | (unsigned)(NCLS - 1 - c);
            if (k > bk) bk = k;
            k = ((unsigned long long)__float_as_uint(tv[it].y) << 32) | (unsigned)(NCLS - 2 - c);
            if (k > bk) bk = k;
            k = ((unsigned long long)__float_as_uint(tv[it].z) << 32) | (unsigned)(NCLS - 3 - c);
            if (k > bk) bk = k;
            k = ((unsigned long long)__float_as_uint(tv[it].w) << 32) | (unsigned)(NCLS - 4 - c);
            if (k > bk) bk = k;
            if (has_next) tv[it] = __ldcs(trowN + it * 32);   // prefetch next row
        }

        #pragma unroll
        for (int off = 16; off; off >>= 1) {
            unsigned long long ok = __shfl_xor_sync(0xFFFFFFFFu, bk, off);
            if (ok > bk) bk = ok;
        }
        if (lane == 0)
            g_t[r] = NCLS - 1 - (int)(bk & 0xFFFFFFFFu);
    }
}

// ---------------------------------------------------------------- kernel B
__device__ __forceinline__ void consume_row(
    const float4 (&yv)[8], int t, int lane, const float* wtab,
    float& acc_pt, double& acc_ce)
{
    // CE: extract y[t] from the owning lane's registers
    if (lane == ((t >> 2) & 31)) {
        const int itq = t >> 7;
        const int cq  = t & 3;
        float4 v = yv[0];
        #pragma unroll
        for (int it = 1; it < 8; it++) if (it == itq) v = yv[it];
        float yt = (cq == 0) ? v.x : (cq == 1) ? v.y : (cq == 2) ? v.z : v.w;
        acc_ce += (double)logf(yt + 1e-8f);
    }

    // weighted sum: factored popcount + 4-way accumulator ILP
    const int tb = t >> 2;
    const int tl = t & 3;
    const int d0 = __popc(tl ^ 0), d1 = __popc(tl ^ 1);
    const int d2 = __popc(tl ^ 2), d3 = __popc(tl ^ 3);

    float p0 = 0.0f, p1 = 0.0f, p2 = 0.0f, p3 = 0.0f;
    #pragma unroll
    for (int it = 0; it < 8; it++) {
        const int cb = it * 32 + lane;
        const int pb = __popc(tb ^ cb);
        p0 = fmaf(wtab[pb + d0], yv[it].x, p0);
        p1 = fmaf(wtab[pb + d1], yv[it].y, p1);
        p2 = fmaf(wtab[pb + d2], yv[it].z, p2);
        p3 = fmaf(wtab[pb + d3], yv[it].w, p3);
    }
    acc_pt += (p0 + p1) + (p2 + p3);
}

__global__ __launch_bounds__(TPB, CPS_B)
void wsum_kernel(const float* __restrict__ y, float* __restrict__ out, int B) {
    __shared__ float  wtab[16];
    __shared__ double s_ce[WPB], s_pt[WPB];

    const int tid  = threadIdx.x;
    const int lane = tid & 31;
    const int wid  = tid >> 5;

    if (tid < 11) {
        float w = 1.0f;
        for (int i = 0; i < tid; i++) w *= 6.0f;   // exact: 6^10 < 2^26
        wtab[tid] = (tid == 0) ? 0.0f : w;
    }
    __syncthreads();

    const int gw = blockIdx.x * WPB + wid;
    const int nw = gridDim.x * WPB;

    float  acc_pt = 0.0f;
    double acc_ce = 0.0;

    float4 yva[8], yvb[8];

    // prologue: load row gw into buffer A (nw <= B: every warp has >= 1 row)
    int ta;
    {
        const float4* yrow = (const float4*)(y + (size_t)gw * NCLS) + lane;
        #pragma unroll
        for (int it = 0; it < 8; it++)
            yva[it] = __ldcs(yrow + it * 32);
        ta = g_t[gw];
    }

    int r = gw;
    while (true) {
        // ---- stage 1: prefetch row r+nw into B (batched), consume A(row r) ----
        const int  rb = r + nw;
        const bool hb = rb < B;                       // warp-uniform
        int tb_ = 0;
        if (hb) {
            const float4* yrowB = (const float4*)(y + (size_t)rb * NCLS) + lane;
            #pragma unroll
            for (int it = 0; it < 8; it++)
                yvb[it] = __ldcs(yrowB + it * 32);
            tb_ = g_t[rb];
        }
        consume_row(yva, ta, lane, wtab, acc_pt, acc_ce);
        if (!hb) break;

        // ---- stage 2: prefetch row rb+nw into A (batched), consume B(row rb) ----
        const int  rc = rb + nw;
        const bool hc = rc < B;
        if (hc) {
            const float4* yrowC = (const float4*)(y + (size_t)rc * NCLS) + lane;
            #pragma unroll
            for (int it = 0; it < 8; it++)
                yva[it] = __ldcs(yrowC + it * 32);
            ta = g_t[rc];
        }
        consume_row(yvb, tb_, lane, wtab, acc_pt, acc_ce);
        if (!hc) break;

        r = rc;
    }

    // warp reduce (once)
    double dpt = (double)acc_pt;
    #pragma unroll
    for (int off = 16; off; off >>= 1) {
        dpt    += __shfl_xor_sync(0xFFFFFFFFu, dpt,    off);
        acc_ce += __shfl_xor_sync(0xFFFFFFFFu, acc_ce, off);
    }
    if (lane == 0) { s_ce[wid] = acc_ce; s_pt[wid] = dpt; }
    __syncthreads();

    // block reduce + fenced last-block finish
    if (tid == 0) {
        double bce = 0.0, bpt = 0.0;
        #pragma unroll
        for (int i = 0; i < WPB; i++) { bce += s_ce[i]; bpt += s_pt[i]; }
        atomicAdd(&g_ce, bce);
        atomicAdd(&g_pt, bpt);
        __threadfence();
        unsigned old = atomicAdd(&g_count, 1u);
        if (old == gridDim.x - 1) {
            double CE = atomicAdd(&g_ce, 0.0);   // L2 read (bypass stale L1)
            double PT = atomicAdd(&g_pt, 0.0);
            out[0] = (float)(-CE / (double)B + PT / ((double)B * (double)NCLS));
            g_ce = 0.0;                           // reset for next graph replay
            g_pt = 0.0;
            g_count = 0u;
        }
    }
}

extern "C" void kernel_launch(void* const* d_in, const int* in_sizes, int n_in,
                              void* d_out, int out_size) {
    const float* y_true = (const float*)d_in[0];
    const float* target = (const float*)d_in[1];
    const int B = in_sizes[0] / NCLS;

    argmax_kernel<<<BLK_A, TPB>>>(target, B);
    wsum_kernel  <<<BLK_B, TPB>>>(y_true, (float*)d_out, B);
}

// round 11
// speedup vs baseline: 1.0147x; 1.0147x over previous
#include <cuda_runtime.h>
#include <math.h>

// Two-kernel split:
//   A: t[b] = argmax(target[b,:])
//   B: out = -mean log(y[b,t_b]+1e-8) + sum_{b,c} w(popc(t_b^c))*y[b,c]/(B*N)
//      w(0)=0, w(p)=6^p.
// Factorization in B: 6^popc(t^c) = 6^popc(tb^cb) * 6^popc(tl^j)
//   (tb=t>>2, cb=c>>2, tl=t&3, j=c&3)
// -> per float4 group: one LDS (base=6^pb) + 4 FMAs into class accumulators
//    q0..q3; low-bit factors {1,6,6,36} applied once per row.
//    c==t exception handled by subtracting y[t] once (f-product there is 1).

#define NCLS   1024
#define MAXB   65536
#define SMS    152
#define TPB    256
#define WPB    (TPB / 32)
#define CPS_A  3
#define CPS_B  3
#define BLK_A  (SMS * CPS_A)
#define BLK_B  (SMS * CPS_B)

__device__ int      g_t[MAXB];
__device__ double   g_ce = 0.0;
__device__ double   g_pt = 0.0;
__device__ unsigned g_count = 0;

// ---------------------------------------------------------------- kernel A
__global__ __launch_bounds__(TPB, CPS_A)
void argmax_kernel(const float* __restrict__ tgt, int B) {
    const int tid  = threadIdx.x;
    const int lane = tid & 31;
    const int wid  = tid >> 5;

    const int gw = blockIdx.x * WPB + wid;
    const int nw = gridDim.x * WPB;

    float4 tv[8];
    {
        const float4* trow = (const float4*)(tgt + (size_t)gw * NCLS) + lane;
        #pragma unroll
        for (int it = 0; it < 8; it++)
            tv[it] = __ldcs(trow + it * 32);
    }

    for (int r = gw; r < B; r += nw) {
        const int  rn       = r + nw;
        const bool has_next = rn < B;                 // warp-uniform
        const float4* trowN = (const float4*)(tgt + (size_t)(has_next ? rn : r) * NCLS) + lane;

        // key = (fbits<<32)|(N-1-idx): positive uniforms -> bits monotonic;
        // complemented idx -> max-key picks FIRST max on ties.
        unsigned long long bk = 0ull;
        #pragma unroll
        for (int it = 0; it < 8; it++) {
            int c = (it * 32 + lane) * 4;
            unsigned long long k;
            k = ((unsigned long long)__float_as_uint(tv[it].x) << 32) | (unsigned)(NCLS - 1 - c);
            if (k > bk) bk = k;
            k = ((unsigned long long)__float_as_uint(tv[it].y) << 32) | (unsigned)(NCLS - 2 - c);
            if (k > bk) bk = k;
            k = ((unsigned long long)__float_as_uint(tv[it].z) << 32) | (unsigned)(NCLS - 3 - c);
            if (k > bk) bk = k;
            k = ((unsigned long long)__float_as_uint(tv[it].w) << 32) | (unsigned)(NCLS - 4 - c);
            if (k > bk) bk = k;
            if (has_next) tv[it] = __ldcs(trowN + it * 32);   // prefetch next row
        }

        #pragma unroll
        for (int off = 16; off; off >>= 1) {
            unsigned long long ok = __shfl_xor_sync(0xFFFFFFFFu, bk, off);
            if (ok > bk) bk = ok;
        }
        if (lane == 0)
            g_t[r] = NCLS - 1 - (int)(bk & 0xFFFFFFFFu);
    }
}

// ---------------------------------------------------------------- kernel B
__global__ __launch_bounds__(TPB, CPS_B)
void wsum_kernel(const float* __restrict__ y, float* __restrict__ out, int B) {
    __shared__ float  wtab[16];      // wtab[k] = 6^k (pure powers; k<=8 used)
    __shared__ double s_ce[WPB], s_pt[WPB];

    const int tid  = threadIdx.x;
    const int lane = tid & 31;
    const int wid  = tid >> 5;

    if (tid < 16) {
        float w = 1.0f;
        for (int i = 0; i < tid && i < 9; i++) w *= 6.0f;   // exact: 6^8 < 2^24
        wtab[tid] = w;
    }
    __syncthreads();

    const int gw = blockIdx.x * WPB + wid;
    const int nw = gridDim.x * WPB;

    float  acc_pt = 0.0f;
    double acc_ce = 0.0;

    float4 yv[8];
    int tcur;
    {
        const float4* yrow = (const float4*)(y + (size_t)gw * NCLS) + lane;
        #pragma unroll
        for (int it = 0; it < 8; it++)
            yv[it] = __ldcs(yrow + it * 32);
        tcur = g_t[gw];
    }

    for (int r = gw; r < B; r += nw) {
        const int  rn       = r + nw;
        const bool has_next = rn < B;                 // warp-uniform
        const float4* yrowN = (const float4*)(y + (size_t)(has_next ? rn : r) * NCLS) + lane;
        const int tn = g_t[has_next ? rn : r];        // prefetch next t early

        const int t  = tcur;
        const int tb = t >> 2;
        const int tl = t & 3;

        float q0 = 0.0f, q1 = 0.0f, q2 = 0.0f, q3 = 0.0f;
        float4 c4 = make_float4(0.f, 0.f, 0.f, 0.f);  // captured float4 containing y[t]

        #pragma unroll
        for (int it = 0; it < 8; it++) {
            const int cb = it * 32 + lane;
            const int pb = __popc(tb ^ cb);
            const float base = wtab[pb];              // single LDS per group
            const float4 v = yv[it];
            q0 = fmaf(base, v.x, q0);
            q1 = fmaf(base, v.y, q1);
            q2 = fmaf(base, v.z, q2);
            q3 = fmaf(base, v.w, q3);
            if (pb == 0) c4 = v;                      // predicated SELs, no branch
            if (has_next) yv[it] = __ldcs(yrowN + it * 32);   // next-row prefetch
        }

        // row-final: apply low-bit factors {1,6,6,36} by class (tl uniform per row)
        const float qA = (tl == 0) ? q0 : (tl == 1) ? q1 : (tl == 2) ? q2 : q3;          // tl^j==0
        const int m1 = tl ^ 1, m2 = tl ^ 2, m3 = tl ^ 3;
        const float qB = (m1 == 0) ? q0 : (m1 == 1) ? q1 : (m1 == 2) ? q2 : q3;          // ==1
        const float qC = (m2 == 0) ? q0 : (m2 == 1) ? q1 : (m2 == 2) ? q2 : q3;          // ==2
        const float qD = (m3 == 0) ? q0 : (m3 == 1) ? q1 : (m3 == 2) ? q2 : q3;          // ==3
        acc_pt += fmaf(36.0f, qD, fmaf(6.0f, qB + qC, qA));

        // CE + c==t correction (owning lane holds c4 = the float4 containing y[t])
        if (lane == ((t >> 2) & 31)) {
            const float yt = (tl == 0) ? c4.x : (tl == 1) ? c4.y : (tl == 2) ? c4.z : c4.w;
            acc_pt -= yt;                              // remove the +1*y[t] included above
            acc_ce += (double)logf(yt + 1e-8f);
        }

        tcur = tn;
    }

    // warp reduce (once)
    double dpt = (double)acc_pt;
    #pragma unroll
    for (int off = 16; off; off >>= 1) {
        dpt    += __shfl_xor_sync(0xFFFFFFFFu, dpt,    off);
        acc_ce += __shfl_xor_sync(0xFFFFFFFFu, acc_ce, off);
    }
    if (lane == 0) { s_ce[wid] = acc_ce; s_pt[wid] = dpt; }
    __syncthreads();

    // block reduce + fenced last-block finish
    if (tid == 0) {
        double bce = 0.0, bpt = 0.0;
        #pragma unroll
        for (int i = 0; i < WPB; i++) { bce += s_ce[i]; bpt += s_pt[i]; }
        atomicAdd(&g_ce, bce);
        atomicAdd(&g_pt, bpt);
        __threadfence();
        unsigned old = atomicAdd(&g_count, 1u);
        if (old == gridDim.x - 1) {
            double CE = atomicAdd(&g_ce, 0.0);   // L2 read (bypass stale L1)
            double PT = atomicAdd(&g_pt, 0.0);
            out[0] = (float)(-CE / (double)B + PT / ((double)B * (double)NCLS));
            g_ce = 0.0;                           // reset for next graph replay
            g_pt = 0.0;
            g_count = 0u;
        }
    }
}

extern "C" void kernel_launch(void* const* d_in, const int* in_sizes, int n_in,
                              void* d_out, int out_size) {
    const float* y_true = (const float*)d_in[0];
    const float* target = (const float*)d_in[1];
    const int B = in_sizes[0] / NCLS;

    argmax_kernel<<<BLK_A, TPB>>>(target, B);
    wsum_kernel  <<<BLK_B, TPB>>>(y_true, (float*)d_out, B);
}

// round 12
// speedup vs baseline: 1.0411x; 1.0260x over previous
#include <cuda_runtime.h>
#include <math.h>

// Fused: out = -mean_b log(y[b, argmax(target_b)] + 1e-8)
//            + sum_{b,c} w(popc(t_b^c)) * y[b,c] / (B*N),  w(0)=0, w(p)=6^p.
// N = 1024 (10 bits). Factorization: 6^popc(t^c) = 6^popc(tb^cb) * 6^popc(tl^j)
// (tb=t>>2, cb=c>>2, tl=t&3, j=c&3) -> per float4 group: 1 LDS + 4 FMA into
// class accumulators q0..q3; low-bit factors {1,6,6,36} once per row; the
// c==t exception handled by subtracting y[t] once (its factored weight is 1).

#define NCLS   1024
#define SMS    152
#define CPS    3
#define BLOCKS (SMS * CPS)
#define TPB    256
#define WPB    (TPB / 32)

__device__ double   g_ce = 0.0;
__device__ double   g_pt = 0.0;
__device__ unsigned g_count = 0;

__global__ __launch_bounds__(TPB, CPS)
void ce_pt_kernel(const float* __restrict__ y, const float* __restrict__ tgt,
                  float* __restrict__ out, int B) {
    __shared__ float  wtab[16];      // wtab[k] = 6^k (pure powers, k<=8 used)
    __shared__ double s_ce[WPB], s_pt[WPB];

    const int tid  = threadIdx.x;
    const int lane = tid & 31;
    const int wid  = tid >> 5;

    if (tid < 16) {
        float w = 1.0f;
        for (int i = 0; i < tid && i < 9; i++) w *= 6.0f;   // exact: 6^8 < 2^24
        wtab[tid] = w;
    }
    __syncthreads();

    const int gw = blockIdx.x * WPB + wid;
    const int nw = gridDim.x * WPB;

    float  acc_pt = 0.0f;
    double acc_ce = 0.0;

    for (int r = gw; r < B; r += nw) {
        const float4* trow = (const float4*)(tgt + (size_t)r * NCLS) + lane;
        const float4* yrow = (const float4*)(y   + (size_t)r * NCLS) + lane;

        // ---- batched preload of both rows: 16 LDG.128 in flight ----
        float4 tv[8], yv[8];
        #pragma unroll
        for (int it = 0; it < 8; it++) {
            tv[it] = __ldcs(trow + it * 32);
            yv[it] = __ldcs(yrow + it * 32);
        }

        // ---- argmax via packed u64 key (fbits<<32)|(N-1-idx) ----
        // positive uniforms -> IEEE bits monotonic; complemented idx = first-max ties.
        unsigned long long bk = 0ull;
        #pragma unroll
        for (int it = 0; it < 8; it++) {
            int c = (it * 32 + lane) * 4;
            unsigned long long k;
            k = ((unsigned long long)__float_as_uint(tv[it].x) << 32) | (unsigned)(NCLS - 1 - c);
            if (k > bk) bk = k;
            k = ((unsigned long long)__float_as_uint(tv[it].y) << 32) | (unsigned)(NCLS - 2 - c);
            if (k > bk) bk = k;
            k = ((unsigned long long)__float_as_uint(tv[it].z) << 32) | (unsigned)(NCLS - 3 - c);
            if (k > bk) bk = k;
            k = ((unsigned long long)__float_as_uint(tv[it].w) << 32) | (unsigned)(NCLS - 4 - c);
            if (k > bk) bk = k;
        }
        #pragma unroll
        for (int off = 16; off; off >>= 1) {
            unsigned long long ok = __shfl_xor_sync(0xFFFFFFFFu, bk, off);
            if (ok > bk) bk = ok;
        }
        const int t  = NCLS - 1 - (int)(bk & 0xFFFFFFFFu);   // uniform in warp
        const int tb = t >> 2;
        const int tl = t & 3;

        // ---- factored weighted sum: 1 LDS + 4 FMA per float4 group ----
        float q0 = 0.0f, q1 = 0.0f, q2 = 0.0f, q3 = 0.0f;
        float4 c4 = make_float4(0.f, 0.f, 0.f, 0.f);   // float4 containing y[t]
        #pragma unroll
        for (int it = 0; it < 8; it++) {
            const int cb = it * 32 + lane;
            const int pb = __popc(tb ^ cb);
            const float base = wtab[pb];
            const float4 v = yv[it];
            q0 = fmaf(base, v.x, q0);
            q1 = fmaf(base, v.y, q1);
            q2 = fmaf(base, v.z, q2);
            q3 = fmaf(base, v.w, q3);
            if (pb == 0) c4 = v;                        // predicated SELs
        }

        // row-final: low-bit factors {1,6,6,36} by class (tl warp-uniform)
        const float qA = (tl == 0) ? q0 : (tl == 1) ? q1 : (tl == 2) ? q2 : q3;   // tl^j==0
        const int m1 = tl ^ 1, m2 = tl ^ 2, m3 = tl ^ 3;
        const float qB = (m1 == 0) ? q0 : (m1 == 1) ? q1 : (m1 == 2) ? q2 : q3;   // ==1
        const float qC = (m2 == 0) ? q0 : (m2 == 1) ? q1 : (m2 == 2) ? q2 : q3;   // ==2
        const float qD = (m3 == 0) ? q0 : (m3 == 1) ? q1 : (m3 == 2) ? q2 : q3;   // ==3
        acc_pt += fmaf(36.0f, qD, fmaf(6.0f, qB + qC, qA));

        // ---- CE + c==t correction (owning lane holds c4) ----
        if (lane == ((t >> 2) & 31)) {
            const float yt = (tl == 0) ? c4.x : (tl == 1) ? c4.y : (tl == 2) ? c4.z : c4.w;
            acc_pt -= yt;                               // remove the +1*y[t] term
            acc_ce += (double)logf(yt + 1e-8f);
        }
    }

    // ---- warp reduce (once) ----
    double dpt = (double)acc_pt;
    #pragma unroll
    for (int off = 16; off; off >>= 1) {
        dpt    += __shfl_xor_sync(0xFFFFFFFFu, dpt,    off);
        acc_ce += __shfl_xor_sync(0xFFFFFFFFu, acc_ce, off);
    }
    if (lane == 0) { s_ce[wid] = acc_ce; s_pt[wid] = dpt; }
    __syncthreads();

    // ---- block reduce + fenced last-block finish ----
    if (tid == 0) {
        double bce = 0.0, bpt = 0.0;
        #pragma unroll
        for (int i = 0; i < WPB; i++) { bce += s_ce[i]; bpt += s_pt[i]; }
        atomicAdd(&g_ce, bce);
        atomicAdd(&g_pt, bpt);
        __threadfence();
        unsigned old = atomicAdd(&g_count, 1u);
        if (old == gridDim.x - 1) {
            double CE = atomicAdd(&g_ce, 0.0);   // L2 read (bypass stale L1)
            double PT = atomicAdd(&g_pt, 0.0);
            out[0] = (float)(-CE / (double)B + PT / ((double)B * (double)NCLS));
            g_ce = 0.0;                           // reset for next graph replay
            g_pt = 0.0;
            g_count = 0u;
        }
    }
}

extern "C" void kernel_launch(void* const* d_in, const int* in_sizes, int n_in,
                              void* d_out, int out_size) {
    const float* y_true = (const float*)d_in[0];
    const float* target = (const float*)d_in[1];
    const int B = in_sizes[0] / NCLS;

    ce_pt_kernel<<<BLOCKS, TPB>>>(y_true, target, (float*)d_out, B);
}